// round 10
// baseline (speedup 1.0000x reference)
#include <cuda_runtime.h>
#include <cuda_fp16.h>

#define F_NODES 16384
#define DEG 8
#define E (F_NODES * DEG)   // 131072
#define B 64
#define H 16
#define LAYERS 10

#define NPB 8               // nodes per block
#define TPN 16              // threads per node (4 batch elems each)

typedef unsigned long long u64;

// x0 kept fp32 only for the FINAL layer residual (exact); all steady-state
// traffic is fp16: x0H residual + fp16 ping-pong. Working set ~69MB << L2.
__device__ float  g_x0T[(size_t)E * B];
__device__ __half g_x0H[(size_t)E * B];
__device__ __half g_hA [(size_t)E * B];
__device__ __half g_hB [(size_t)E * B];

__device__ __forceinline__ u64 pack2(float lo, float hi) {
    u64 r; asm("mov.b64 %0, {%1, %2};" : "=l"(r) : "f"(lo), "f"(hi)); return r;
}
__device__ __forceinline__ void unpack2(u64 v, float& lo, float& hi) {
    asm("mov.b64 {%0, %1}, %2;" : "=f"(lo), "=f"(hi) : "l"(v));
}
__device__ __forceinline__ void fma2(u64& d, u64 a, u64 b, u64 c) {
    asm("fma.rn.f32x2 %0, %1, %2, %3;" : "=l"(d) : "l"(a), "l"(b), "l"(c));
}
__device__ __forceinline__ u64 add2(u64 a, u64 b) {
    u64 r; asm("add.rn.f32x2 %0, %1, %2;" : "=l"(r) : "l"(a), "l"(b)); return r;
}
// ELU via select: FMUL+MUFU+FADD+FSETP+FSEL, no branch.
__device__ __forceinline__ float elu1(float x) {
    float e = __expf(x) - 1.0f;
    return x > 0.0f ? x : e;
}

// Per-node smem weights.
struct __align__(16) NodeW {
    u64   sb1[16];     // b1 splats (bj, bj)
    u64   sb2p[4];     // b2 pairs (b2[2k], b2[2k+1]) -- raw order
    float w1[128];     // W1[j][d], j-major (raw global layout)
    float w2t[128];    // W2 column-major: w2t[j*8 + d] = W2[d][j]
    u64   pad[2];
};

// (B, E) row-major -> (E, B) fp32 (final-layer residual) + fp16 (everything else)
__global__ void k_transpose_in(const float* __restrict__ in,
                               float* __restrict__ outf, __half* __restrict__ outh) {
    __shared__ float t[32][33];
    int e0 = blockIdx.x * 32, b0 = blockIdx.y * 32;
    int tx = threadIdx.x, ty = threadIdx.y;
    t[ty][tx] = in[(size_t)(b0 + ty) * E + e0 + tx];
    __syncthreads();
    float v = t[tx][ty];
    size_t o = (size_t)(e0 + ty) * B + b0 + tx;
    outf[o] = v;
    outh[o] = __float2half(v);
}

// One GSNN layer in (E, B) space. 16 threads/node, 4 batch elems/thread.
// Math fp32; x read/written fp16. Non-final: residual from fp16 x0H.
// Final: residual from fp32 x0T, fp32 (B,E) output via register transpose.
__global__ __launch_bounds__(NPB * TPN, 6)
void layer_kernel(const __half* __restrict__ src, __half* __restrict__ dsth,
                  float* __restrict__ dstf,
                  const float* __restrict__ W1, const float* __restrict__ b1,
                  const float* __restrict__ W2, const float* __restrict__ b2,
                  const int* __restrict__ in_ixs,
                  const __half* __restrict__ x0H, const float* __restrict__ x0T,
                  int final_flag) {
    __shared__ NodeW sw[NPB];
    const int tid  = threadIdx.x;
    const int nl   = tid >> 4;        // node within block
    const int q    = tid & 15;        // batch-quad: handles b = 4q..4q+3
    const int node = blockIdx.x * NPB + nl;
    NodeW& nw = sw[nl];

    // Issue gathers first (longest latency); 8B (4 halves) per thread per column.
    const int4 c0 = ((const int4*)(in_ixs + (size_t)node * 8))[0];
    const int4 c1 = ((const int4*)(in_ixs + (size_t)node * 8))[1];
    const int cols[8] = {c0.x, c0.y, c0.z, c0.w, c1.x, c1.y, c1.z, c1.w};
    uint2 gh[8];
#pragma unroll
    for (int d = 0; d < 8; d++)
        gh[d] = *(const uint2*)(src + (((size_t)cols[d]) << 6) + (q << 2));

    // Stage weights (plain loads).
    {
        const float4* gW1 = (const float4*)(W1 + (size_t)node * 128);
        ((float4*)nw.w1)[q * 2]     = gW1[q * 2];
        ((float4*)nw.w1)[q * 2 + 1] = gW1[q * 2 + 1];
        const float* gW2 = W2 + (size_t)node * 128;   // [d][j]
#pragma unroll
        for (int d = 0; d < 8; d++)
            nw.w2t[q * 8 + d] = gW2[d * 16 + q];      // w2t[j=q][d]
        float bj = b1[(size_t)node * 16 + q];
        nw.sb1[q] = pack2(bj, bj);
        if (q < 4)
            nw.sb2p[q] = *(const u64*)(b2 + (size_t)node * 8 + q * 2);
    }
    __syncthreads();

    // Convert gathered halves to packed fp32 batch-pairs.
    u64 g0[8], g1[8];
#pragma unroll
    for (int d = 0; d < 8; d++) {
        __half2 ha = *(__half2*)&gh[d].x;
        __half2 hb = *(__half2*)&gh[d].y;
        float2 fa = __half22float2(ha);
        float2 fb = __half22float2(hb);
        g0[d] = pack2(fa.x, fa.y);
        g1[d] = pack2(fb.x, fb.y);
    }

    // Output accumulators o[k][b]: lanes = out-dim pair (2k, 2k+1), per batch b.
    u64 o[4][4];
#pragma unroll
    for (int k = 0; k < 4; k++) {
        const u64 bp = nw.sb2p[k];
        o[k][0] = bp; o[k][1] = bp; o[k][2] = bp; o[k][3] = bp;
    }

#pragma unroll
    for (int j = 0; j < 16; j++) {
        // W1 row j: 8 weights via 2x LDS.128, splat to pairs.
        const float4 wA = ((const float4*)(nw.w1 + j * 8))[0];
        const float4 wB = ((const float4*)(nw.w1 + j * 8))[1];
        u64 s[8];
        s[0] = pack2(wA.x, wA.x); s[1] = pack2(wA.y, wA.y);
        s[2] = pack2(wA.z, wA.z); s[3] = pack2(wA.w, wA.w);
        s[4] = pack2(wB.x, wB.x); s[5] = pack2(wB.y, wB.y);
        s[6] = pack2(wB.z, wB.z); s[7] = pack2(wB.w, wB.w);

        // Two 4-deep chains per batch pair, then combine.
        u64 pA = nw.sb1[j], pB = 0, pC = pA, pD = 0;
#pragma unroll
        for (int d = 0; d < 4; d++) {
            fma2(pA, g0[d], s[d], pA);
            fma2(pB, g0[d + 4], s[d + 4], pB);
            fma2(pC, g1[d], s[d], pC);
            fma2(pD, g1[d + 4], s[d + 4], pD);
        }
        u64 a0 = add2(pA, pB);
        u64 a1 = add2(pC, pD);

        float h0, h1, h2, h3;
        unpack2(a0, h0, h1);
        unpack2(a1, h2, h3);
        h0 = elu1(h0); h1 = elu1(h1); h2 = elu1(h2); h3 = elu1(h3);
        const u64 hs0 = pack2(h0, h0), hs1 = pack2(h1, h1);
        const u64 hs2 = pack2(h2, h2), hs3 = pack2(h3, h3);

        // W2 column j consumed as packed d-pairs straight from LDS.128 (no splats).
        const float4 vA = ((const float4*)(nw.w2t + j * 8))[0];
        const float4 vB = ((const float4*)(nw.w2t + j * 8))[1];
        const u64 w2q0 = pack2(vA.x, vA.y), w2q1 = pack2(vA.z, vA.w);
        const u64 w2q2 = pack2(vB.x, vB.y), w2q3 = pack2(vB.z, vB.w);
        fma2(o[0][0], hs0, w2q0, o[0][0]); fma2(o[0][1], hs1, w2q0, o[0][1]);
        fma2(o[0][2], hs2, w2q0, o[0][2]); fma2(o[0][3], hs3, w2q0, o[0][3]);
        fma2(o[1][0], hs0, w2q1, o[1][0]); fma2(o[1][1], hs1, w2q1, o[1][1]);
        fma2(o[1][2], hs2, w2q1, o[1][2]); fma2(o[1][3], hs3, w2q1, o[1][3]);
        fma2(o[2][0], hs0, w2q2, o[2][0]); fma2(o[2][1], hs1, w2q2, o[2][1]);
        fma2(o[2][2], hs2, w2q2, o[2][2]); fma2(o[2][3], hs3, w2q2, o[2][3]);
        fma2(o[3][0], hs0, w2q3, o[3][0]); fma2(o[3][1], hs1, w2q3, o[3][1]);
        fma2(o[3][2], hs2, w2q3, o[3][2]); fma2(o[3][3], hs3, w2q3, o[3][3]);
    }

    // Extract out[d][b] scalars (lane extracts are register aliases).
    float ov[8][4];
#pragma unroll
    for (int k = 0; k < 4; k++)
#pragma unroll
        for (int b = 0; b < 4; b++) {
            float lo, hi;
            unpack2(o[k][b], lo, hi);
            ov[2 * k][b]     = lo;
            ov[2 * k + 1][b] = hi;
        }

    if (!final_flag) {
        // Residual from fp16 x0H (halves steady-state residual traffic) + fp16 store.
#pragma unroll
        for (int d = 0; d < 8; d++) {
            const size_t col = (size_t)node * 8 + d;
            const uint2 rh = *(const uint2*)(x0H + (col << 6) + (q << 2));
            const float2 ra = __half22float2(*(__half2*)&rh.x);
            const float2 rb = __half22float2(*(__half2*)&rh.y);
            __half2 ha = __floats2half2_rn(ov[d][0] + ra.x, ov[d][1] + ra.y);
            __half2 hb = __floats2half2_rn(ov[d][2] + rb.x, ov[d][3] + rb.y);
            uint2 st; st.x = *(unsigned*)&ha; st.y = *(unsigned*)&hb;
            *(uint2*)(dsth + (col << 6) + (q << 2)) = st;
        }
    } else {
        // Final layer: exact fp32 residual + register transpose + fp32 (B,E) store.
        float ob[4][8];
#pragma unroll
        for (int d = 0; d < 8; d++) {
            const size_t col = (size_t)node * 8 + d;
            const float4 r = *(const float4*)(x0T + (col << 6) + (q << 2));
            ob[0][d] = ov[d][0] + r.x; ob[1][d] = ov[d][1] + r.y;
            ob[2][d] = ov[d][2] + r.z; ob[3][d] = ov[d][3] + r.w;
        }
#pragma unroll
        for (int rr = 0; rr < 4; rr++) {
            float* p = dstf + (size_t)(q * 4 + rr) * E + (size_t)node * 8;
            *(float4*)(p)     = make_float4(ob[rr][0], ob[rr][1], ob[rr][2], ob[rr][3]);
            *(float4*)(p + 4) = make_float4(ob[rr][4], ob[rr][5], ob[rr][6], ob[rr][7]);
        }
    }
}

extern "C" void kernel_launch(void* const* d_in, const int* in_sizes, int n_in,
                              void* d_out, int out_size) {
    const float* x0     = (const float*)d_in[0];
    const float* W1     = (const float*)d_in[1];
    const float* b1     = (const float*)d_in[2];
    const float* W2     = (const float*)d_in[3];
    const float* b2     = (const float*)d_in[4];
    const int*   in_ixs = (const int*)d_in[5];
    float* out = (float*)d_out;

    float *x0T;
    __half *x0H, *hA, *hB;
    cudaGetSymbolAddress((void**)&x0T, g_x0T);
    cudaGetSymbolAddress((void**)&x0H, g_x0H);
    cudaGetSymbolAddress((void**)&hA,  g_hA);
    cudaGetSymbolAddress((void**)&hB,  g_hB);

    k_transpose_in<<<dim3(E / 32, B / 32), dim3(32, 32)>>>(x0, x0T, x0H);

    const __half* src = x0H;
    __half* bufs[2] = {hA, hB};
    for (int L = 0; L < LAYERS; L++) {
        const int fin = (L == LAYERS - 1);
        __half* dh = fin ? nullptr : bufs[L & 1];
        layer_kernel<<<F_NODES / NPB, NPB * TPN>>>(src, dh, fin ? out : nullptr,
                                                   W1, b1, W2, b2, in_ixs,
                                                   x0H, x0T, fin);
        src = dh;
    }
}

// round 11
// speedup vs baseline: 1.2134x; 1.2134x over previous
#include <cuda_runtime.h>
#include <cuda_fp16.h>

#define F_NODES 16384
#define DEG 8
#define E (F_NODES * DEG)   // 131072
#define B 64
#define H 16
#define LAYERS 10

#define NPB 8               // nodes per block
#define TPN 16              // threads per node (4 batch elems each)

typedef unsigned long long u64;

// x0 kept fp32 only for the FINAL layer residual (exact); all steady-state
// traffic is fp16: x0H residual + fp16 ping-pong. Working set ~69MB << L2.
__device__ float  g_x0T[(size_t)E * B];
__device__ __half g_x0H[(size_t)E * B];
__device__ __half g_hA [(size_t)E * B];
__device__ __half g_hB [(size_t)E * B];

__device__ __forceinline__ u64 pack2(float lo, float hi) {
    u64 r; asm("mov.b64 %0, {%1, %2};" : "=l"(r) : "f"(lo), "f"(hi)); return r;
}
__device__ __forceinline__ void unpack2(u64 v, float& lo, float& hi) {
    asm("mov.b64 {%0, %1}, %2;" : "=f"(lo), "=f"(hi) : "l"(v));
}
__device__ __forceinline__ void fma2(u64& d, u64 a, u64 b, u64 c) {
    asm("fma.rn.f32x2 %0, %1, %2, %3;" : "=l"(d) : "l"(a), "l"(b), "l"(c));
}
__device__ __forceinline__ u64 add2(u64 a, u64 b) {
    u64 r; asm("add.rn.f32x2 %0, %1, %2;" : "=l"(r) : "l"(a), "l"(b)); return r;
}
// ELU via select: FMUL+MUFU+FADD+FSETP+FSEL, no branch.
__device__ __forceinline__ float elu1(float x) {
    float e = __expf(x) - 1.0f;
    return x > 0.0f ? x : e;
}

// Per-node smem weights.
struct __align__(16) NodeW {
    u64   sb1[16];     // b1 splats (bj, bj)
    u64   sb2p[4];     // b2 pairs (b2[2k], b2[2k+1]) -- raw order
    float w1[128];     // W1[j][d], j-major (raw global layout)
    float w2t[128];    // W2 column-major: w2t[j*8 + d] = W2[d][j]
    u64   pad[2];
};

// (B, E) row-major -> (E, B) fp32 (final-layer residual) + fp16 (everything else)
__global__ void k_transpose_in(const float* __restrict__ in,
                               float* __restrict__ outf, __half* __restrict__ outh) {
    __shared__ float t[32][33];
    int e0 = blockIdx.x * 32, b0 = blockIdx.y * 32;
    int tx = threadIdx.x, ty = threadIdx.y;
    t[ty][tx] = in[(size_t)(b0 + ty) * E + e0 + tx];
    __syncthreads();
    float v = t[tx][ty];
    size_t o = (size_t)(e0 + ty) * B + b0 + tx;
    outf[o] = v;
    outh[o] = __float2half(v);
}

// One GSNN layer in (E, B) space. 16 threads/node, 4 batch elems/thread.
// Math fp32; x read/written fp16. Non-final: residual from fp16 x0H.
// Final: residual from fp32 x0T, fp32 (B,E) output via register transpose.
// NOTE: no min-blocks clause -- capping regs to 80 caused spills (R10).
__global__ __launch_bounds__(NPB * TPN)
void layer_kernel(const __half* __restrict__ src, __half* __restrict__ dsth,
                  float* __restrict__ dstf,
                  const float* __restrict__ W1, const float* __restrict__ b1,
                  const float* __restrict__ W2, const float* __restrict__ b2,
                  const int* __restrict__ in_ixs,
                  const __half* __restrict__ x0H, const float* __restrict__ x0T,
                  int final_flag) {
    __shared__ NodeW sw[NPB];
    const int tid  = threadIdx.x;
    const int nl   = tid >> 4;        // node within block
    const int q    = tid & 15;        // batch-quad: handles b = 4q..4q+3
    const int node = blockIdx.x * NPB + nl;
    NodeW& nw = sw[nl];

    // Issue gathers first (longest latency); 8B (4 halves) per thread per column.
    const int4 c0 = ((const int4*)(in_ixs + (size_t)node * 8))[0];
    const int4 c1 = ((const int4*)(in_ixs + (size_t)node * 8))[1];
    const int cols[8] = {c0.x, c0.y, c0.z, c0.w, c1.x, c1.y, c1.z, c1.w};
    uint2 gh[8];
#pragma unroll
    for (int d = 0; d < 8; d++)
        gh[d] = *(const uint2*)(src + (((size_t)cols[d]) << 6) + (q << 2));

    // Stage weights (plain loads).
    {
        const float4* gW1 = (const float4*)(W1 + (size_t)node * 128);
        ((float4*)nw.w1)[q * 2]     = gW1[q * 2];
        ((float4*)nw.w1)[q * 2 + 1] = gW1[q * 2 + 1];
        const float* gW2 = W2 + (size_t)node * 128;   // [d][j]
#pragma unroll
        for (int d = 0; d < 8; d++)
            nw.w2t[q * 8 + d] = gW2[d * 16 + q];      // w2t[j=q][d]
        float bj = b1[(size_t)node * 16 + q];
        nw.sb1[q] = pack2(bj, bj);
        if (q < 4)
            nw.sb2p[q] = *(const u64*)(b2 + (size_t)node * 8 + q * 2);
    }
    __syncthreads();

    // Convert gathered halves to packed fp32 batch-pairs.
    u64 g0[8], g1[8];
#pragma unroll
    for (int d = 0; d < 8; d++) {
        __half2 ha = *(__half2*)&gh[d].x;
        __half2 hb = *(__half2*)&gh[d].y;
        float2 fa = __half22float2(ha);
        float2 fb = __half22float2(hb);
        g0[d] = pack2(fa.x, fa.y);
        g1[d] = pack2(fb.x, fb.y);
    }

    // Output accumulators o[k][b]: lanes = out-dim pair (2k, 2k+1), per batch b.
    u64 o[4][4];
#pragma unroll
    for (int k = 0; k < 4; k++) {
        const u64 bp = nw.sb2p[k];
        o[k][0] = bp; o[k][1] = bp; o[k][2] = bp; o[k][3] = bp;
    }

#pragma unroll
    for (int j = 0; j < 16; j++) {
        // W1 row j: 8 weights via 2x LDS.128, splat to pairs.
        const float4 wA = ((const float4*)(nw.w1 + j * 8))[0];
        const float4 wB = ((const float4*)(nw.w1 + j * 8))[1];
        u64 s[8];
        s[0] = pack2(wA.x, wA.x); s[1] = pack2(wA.y, wA.y);
        s[2] = pack2(wA.z, wA.z); s[3] = pack2(wA.w, wA.w);
        s[4] = pack2(wB.x, wB.x); s[5] = pack2(wB.y, wB.y);
        s[6] = pack2(wB.z, wB.z); s[7] = pack2(wB.w, wB.w);

        // Two 4-deep chains per batch pair, then combine.
        u64 pA = nw.sb1[j], pB = 0, pC = pA, pD = 0;
#pragma unroll
        for (int d = 0; d < 4; d++) {
            fma2(pA, g0[d], s[d], pA);
            fma2(pB, g0[d + 4], s[d + 4], pB);
            fma2(pC, g1[d], s[d], pC);
            fma2(pD, g1[d + 4], s[d + 4], pD);
        }
        u64 a0 = add2(pA, pB);
        u64 a1 = add2(pC, pD);

        float h0, h1, h2, h3;
        unpack2(a0, h0, h1);
        unpack2(a1, h2, h3);
        h0 = elu1(h0); h1 = elu1(h1); h2 = elu1(h2); h3 = elu1(h3);
        const u64 hs0 = pack2(h0, h0), hs1 = pack2(h1, h1);
        const u64 hs2 = pack2(h2, h2), hs3 = pack2(h3, h3);

        // W2 column j consumed as packed d-pairs straight from LDS.128 (no splats).
        const float4 vA = ((const float4*)(nw.w2t + j * 8))[0];
        const float4 vB = ((const float4*)(nw.w2t + j * 8))[1];
        const u64 w2q0 = pack2(vA.x, vA.y), w2q1 = pack2(vA.z, vA.w);
        const u64 w2q2 = pack2(vB.x, vB.y), w2q3 = pack2(vB.z, vB.w);
        fma2(o[0][0], hs0, w2q0, o[0][0]); fma2(o[0][1], hs1, w2q0, o[0][1]);
        fma2(o[0][2], hs2, w2q0, o[0][2]); fma2(o[0][3], hs3, w2q0, o[0][3]);
        fma2(o[1][0], hs0, w2q1, o[1][0]); fma2(o[1][1], hs1, w2q1, o[1][1]);
        fma2(o[1][2], hs2, w2q1, o[1][2]); fma2(o[1][3], hs3, w2q1, o[1][3]);
        fma2(o[2][0], hs0, w2q2, o[2][0]); fma2(o[2][1], hs1, w2q2, o[2][1]);
        fma2(o[2][2], hs2, w2q2, o[2][2]); fma2(o[2][3], hs3, w2q2, o[2][3]);
        fma2(o[3][0], hs0, w2q3, o[3][0]); fma2(o[3][1], hs1, w2q3, o[3][1]);
        fma2(o[3][2], hs2, w2q3, o[3][2]); fma2(o[3][3], hs3, w2q3, o[3][3]);
    }

    // Extract out[d][b] scalars (lane extracts are register aliases).
    float ov[8][4];
#pragma unroll
    for (int k = 0; k < 4; k++)
#pragma unroll
        for (int b = 0; b < 4; b++) {
            float lo, hi;
            unpack2(o[k][b], lo, hi);
            ov[2 * k][b]     = lo;
            ov[2 * k + 1][b] = hi;
        }

    if (!final_flag) {
        // Residual from fp16 x0H (halves steady-state residual traffic) + fp16 store.
#pragma unroll
        for (int d = 0; d < 8; d++) {
            const size_t col = (size_t)node * 8 + d;
            const uint2 rh = *(const uint2*)(x0H + (col << 6) + (q << 2));
            const float2 ra = __half22float2(*(__half2*)&rh.x);
            const float2 rb = __half22float2(*(__half2*)&rh.y);
            __half2 ha = __floats2half2_rn(ov[d][0] + ra.x, ov[d][1] + ra.y);
            __half2 hb = __floats2half2_rn(ov[d][2] + rb.x, ov[d][3] + rb.y);
            uint2 st; st.x = *(unsigned*)&ha; st.y = *(unsigned*)&hb;
            *(uint2*)(dsth + (col << 6) + (q << 2)) = st;
        }
    } else {
        // Final layer: exact fp32 residual + register transpose + fp32 (B,E) store.
        float ob[4][8];
#pragma unroll
        for (int d = 0; d < 8; d++) {
            const size_t col = (size_t)node * 8 + d;
            const float4 r = *(const float4*)(x0T + (col << 6) + (q << 2));
            ob[0][d] = ov[d][0] + r.x; ob[1][d] = ov[d][1] + r.y;
            ob[2][d] = ov[d][2] + r.z; ob[3][d] = ov[d][3] + r.w;
        }
#pragma unroll
        for (int rr = 0; rr < 4; rr++) {
            float* p = dstf + (size_t)(q * 4 + rr) * E + (size_t)node * 8;
            *(float4*)(p)     = make_float4(ob[rr][0], ob[rr][1], ob[rr][2], ob[rr][3]);
            *(float4*)(p + 4) = make_float4(ob[rr][4], ob[rr][5], ob[rr][6], ob[rr][7]);
        }
    }
}

extern "C" void kernel_launch(void* const* d_in, const int* in_sizes, int n_in,
                              void* d_out, int out_size) {
    const float* x0     = (const float*)d_in[0];
    const float* W1     = (const float*)d_in[1];
    const float* b1     = (const float*)d_in[2];
    const float* W2     = (const float*)d_in[3];
    const float* b2     = (const float*)d_in[4];
    const int*   in_ixs = (const int*)d_in[5];
    float* out = (float*)d_out;

    float *x0T;
    __half *x0H, *hA, *hB;
    cudaGetSymbolAddress((void**)&x0T, g_x0T);
    cudaGetSymbolAddress((void**)&x0H, g_x0H);
    cudaGetSymbolAddress((void**)&hA,  g_hA);
    cudaGetSymbolAddress((void**)&hB,  g_hB);

    k_transpose_in<<<dim3(E / 32, B / 32), dim3(32, 32)>>>(x0, x0T, x0H);

    const __half* src = x0H;
    __half* bufs[2] = {hA, hB};
    for (int L = 0; L < LAYERS; L++) {
        const int fin = (L == LAYERS - 1);
        __half* dh = fin ? nullptr : bufs[L & 1];
        layer_kernel<<<F_NODES / NPB, NPB * TPN>>>(src, dh, fin ? out : nullptr,
                                                   W1, b1, W2, b2, in_ixs,
                                                   x0H, x0T, fin);
        src = dh;
    }
}